// round 1
// baseline (speedup 1.0000x reference)
#include <cuda_runtime.h>

// Problem constants
#define BATCH 4
#define HEADS 8
#define MID 16
#define HALF 8
#define G 4
#define COUT 64
#define WDIM 28
#define NPOS 784           // 28*28
#define NREL 110           // 2*(2W-1)
#define SCALE 0.5773502691896258f   // 1/sqrt(3)

// ---------------- device scratch (no allocations allowed) ----------------
__device__ float d_q[BATCH*HEADS*MID*NPOS];
__device__ float d_k[BATCH*HEADS*MID*NPOS];
__device__ float d_v[BATCH*HEADS*MID*NPOS];
__device__ float d_Er[NREL*HALF];
__device__ float d_Ec[NREL*HALF];
__device__ float d_outv[BATCH*G*NPOS*(MID*HEADS)];   // [b][g][pos][m*8+h]

// ---------------- embedding MLP: 220 rows, trivial ----------------
__global__ void embed_kernel(
    const float* __restrict__ w1r, const float* __restrict__ b1r,
    const float* __restrict__ gr,  const float* __restrict__ ber,
    const float* __restrict__ w2r, const float* __restrict__ b2r,
    const float* __restrict__ w1c, const float* __restrict__ b1c,
    const float* __restrict__ gc,  const float* __restrict__ bec,
    const float* __restrict__ w2c, const float* __restrict__ b2c)
{
    int t = threadIdx.x;
    if (t >= 2*NREL) return;
    bool isRow = (t < NREL);
    int a = isRow ? t : t - NREL;
    const float* w1 = isRow ? w1r : w1c;
    const float* b1 = isRow ? b1r : b1c;
    const float* ga = isRow ? gr  : gc;
    const float* be = isRow ? ber : bec;
    const float* w2 = isRow ? w2r : w2c;
    const float* b2 = isRow ? b2r : b2c;

    float u;
    if (a < 55) u = a * (2.0f/54.0f) - 1.0f;
    else        u = -((a-55) * (2.0f/54.0f) - 1.0f);

    float h[16];
    float mu = 0.f;
#pragma unroll
    for (int c = 0; c < 16; c++) { h[c] = u*w1[c] + b1[c]; mu += h[c]; }
    mu *= (1.0f/16.0f);
    float var = 0.f;
#pragma unroll
    for (int c = 0; c < 16; c++) { float d = h[c]-mu; var += d*d; }
    var *= (1.0f/16.0f);
    float inv = rsqrtf(var + 1e-5f);
#pragma unroll
    for (int c = 0; c < 16; c++) {
        float hn = ga[c]*(h[c]-mu)*inv + be[c];
        h[c] = hn / (1.0f + expf(-hn));   // swish
    }
    float* out = isRow ? d_Er : d_Ec;
#pragma unroll
    for (int d = 0; d < HALF; d++) {
        float s = b2[d];
#pragma unroll
        for (int c = 0; c < 16; c++) s += h[c]*w2[d*16+c];
        out[a*HALF + d] = s;
    }
}

// ---------------- q/k/v 1x1 conv ----------------
// layout out: [b][h][m][pos], h = o%8, m = o/8
__global__ void qkv_kernel(
    const float* __restrict__ x,
    const float* __restrict__ wq, const float* __restrict__ bq,
    const float* __restrict__ wk, const float* __restrict__ bk,
    const float* __restrict__ wv, const float* __restrict__ bv)
{
    int idx = blockIdx.x*blockDim.x + threadIdx.x;
    if (idx >= BATCH*128*NPOS) return;
    int pos = idx % NPOS;
    int o   = (idx / NPOS) % 128;
    int b   = idx / (NPOS*128);
    float x0 = x[(b*3+0)*NPOS + pos];
    float x1 = x[(b*3+1)*NPOS + pos];
    float x2 = x[(b*3+2)*NPOS + pos];
    float q = bq[o] + wq[o*3+0]*x0 + wq[o*3+1]*x1 + wq[o*3+2]*x2;
    float k = bk[o] + wk[o*3+0]*x0 + wk[o*3+1]*x1 + wk[o*3+2]*x2;
    float v = bv[o] + wv[o*3+0]*x0 + wv[o*3+1]*x1 + wv[o*3+2]*x2;
    int h = o & 7, m = o >> 3;
    int dst = ((b*HEADS + h)*MID + m)*NPOS + pos;
    d_q[dst] = q; d_k[dst] = k; d_v[dst] = v;
}

// ---------------- block reduce helper (4 independent values) ----------------
template<int OP>  // 0 = max, 1 = sum
__device__ __forceinline__ void blockReduce4(float v[4], float* red, int t)
{
#pragma unroll
    for (int off = 16; off; off >>= 1) {
#pragma unroll
        for (int g = 0; g < 4; g++) {
            float o = __shfl_xor_sync(0xffffffffu, v[g], off);
            v[g] = OP ? (v[g] + o) : fmaxf(v[g], o);
        }
    }
    if ((t & 31) == 0) {
#pragma unroll
        for (int g = 0; g < 4; g++) red[(t>>5)*4 + g] = v[g];
    }
    __syncthreads();
#pragma unroll
    for (int g = 0; g < 4; g++) {
        float r = red[g];
#pragma unroll
        for (int w = 1; w < 8; w++) {
            float o = red[w*4 + g];
            r = OP ? (r + o) : fmaxf(r, o);
        }
        v[g] = r;
    }
    __syncthreads();
}

// ---------------- fused attention: one CTA per (b,h,i) ----------------
// smem float layout:
//   ksh[16*784]           @ 0
//   vsh[16*784]           @ 12544
//   Ersh[110*8]           @ 25088
//   Ecsh[110*8]           @ 25968
//   fRsh[110]             @ 26848
//   fCsh[110]             @ 26958
//   qsh[16]               @ 27068
//   red[32]               @ 27084
//   vred[8*64]            @ 27116
// total 27628 floats = 110512 B
#define SMEM_FLOATS 27628

__global__ void __launch_bounds__(256, 2) attn_kernel()
{
    extern __shared__ float smem[];
    float* ksh  = smem;
    float* vsh  = smem + 12544;
    float* Ersh = smem + 25088;
    float* Ecsh = smem + 25968;
    float* fRsh = smem + 26848;
    float* fCsh = smem + 26958;
    float* qsh  = smem + 27068;
    float* red  = smem + 27084;
    float* vred = smem + 27116;

    int t  = threadIdx.x;
    int bx = blockIdx.x;
    int i  = bx % WDIM;
    int h  = (bx / WDIM) % HEADS;
    int b  = bx / (WDIM*HEADS);

    const float* gk = d_k + (size_t)(b*HEADS + h)*MID*NPOS;
    const float* gv = d_v + (size_t)(b*HEADS + h)*MID*NPOS;
    const float* gq = d_q + (size_t)(b*HEADS + h)*MID*NPOS;

    // bulk load K, V tiles (contiguous 12544 floats each)
    {
        const float4* gk4 = (const float4*)gk;
        const float4* gv4 = (const float4*)gv;
        float4* k4 = (float4*)ksh;
        float4* v4 = (float4*)vsh;
        for (int idx = t; idx < 3136; idx += 256) {
            k4[idx] = gk4[idx];
            v4[idx] = gv4[idx];
        }
        for (int idx = t; idx < NREL*HALF; idx += 256) {
            Ersh[idx] = d_Er[idx];
            Ecsh[idx] = d_Ec[idx];
        }
    }
    __syncthreads();

    for (int j = 0; j < WDIM; j++) {
        // load q for this (i,j)
        if (t < 16) qsh[t] = gq[t*NPOS + i*WDIM + j];
        __syncthreads();

        // per-row lookup tables: fR(a) = q[0:8].E_row[a], fC(a) = q[8:16].E_col[a]
        if (t < NREL) {
            float s = 0.f;
#pragma unroll
            for (int c = 0; c < HALF; c++) s += qsh[c]*Ersh[t*HALF + c];
            fRsh[t] = s;
        } else if (t >= 128 && t < 128 + NREL) {
            int a = t - 128;
            float s = 0.f;
#pragma unroll
            for (int c = 0; c < HALF; c++) s += qsh[HALF + c]*Ecsh[a*HALF + c];
            fCsh[a] = s;
        }
        float qreg[16];
#pragma unroll
        for (int m = 0; m < 16; m++) qreg[m] = qsh[m];
        __syncthreads();

        // ---- score phase: each thread owns up to 4 positions, 4 rotations each
        float e[4][4];
        float mx[4] = {-1e30f, -1e30f, -1e30f, -1e30f};
#pragma unroll
        for (int s = 0; s < 4; s++) {
            int pos = t + 256*s;
            if (pos < NPOS) {
                float qk = 0.f;
#pragma unroll
                for (int m = 0; m < 16; m++) qk += qreg[m]*ksh[m*NPOS + pos];
                int kk = pos / WDIM;
                int ll = pos - kk*WDIM;
                int R = kk - i + 27;     // rel(i,k) in [0,54]
                int C = ll - j + 27;     // rel(j,l) in [0,54]
                float s0 = qk + fRsh[R]      + fCsh[C];
                float s1 = qk + fRsh[C + 55] + fCsh[R];
                float s2 = qk + fRsh[R + 55] + fCsh[C + 55];
                float s3 = qk + fRsh[C]      + fCsh[R + 55];
                e[s][0] = s0; mx[0] = fmaxf(mx[0], s0);
                e[s][1] = s1; mx[1] = fmaxf(mx[1], s1);
                e[s][2] = s2; mx[2] = fmaxf(mx[2], s2);
                e[s][3] = s3; mx[3] = fmaxf(mx[3], s3);
            } else {
                e[s][0] = e[s][1] = e[s][2] = e[s][3] = -1e30f;
            }
        }

        blockReduce4<0>(mx, red, t);

        float sum[4] = {0.f, 0.f, 0.f, 0.f};
#pragma unroll
        for (int s = 0; s < 4; s++) {
#pragma unroll
            for (int g = 0; g < 4; g++) {
                float ee = __expf((e[s][g] - mx[g]) * SCALE);
                e[s][g] = ee;          // invalid pos -> underflows to 0
                sum[g] += ee;
            }
        }

        blockReduce4<1>(sum, red, t);

        // ---- P.V accumulation: acc[g*16+m]
        float acc[64];
#pragma unroll
        for (int idx = 0; idx < 64; idx++) acc[idx] = 0.f;
#pragma unroll
        for (int s = 0; s < 4; s++) {
            int pos = t + 256*s;
            if (pos < NPOS) {
#pragma unroll
                for (int m = 0; m < 16; m++) {
                    float vm = vsh[m*NPOS + pos];
                    acc[ 0 + m] += e[s][0]*vm;
                    acc[16 + m] += e[s][1]*vm;
                    acc[32 + m] += e[s][2]*vm;
                    acc[48 + m] += e[s][3]*vm;
                }
            }
        }

        // reduce 64 accumulators across the block
        int lane = t & 31, wp = t >> 5;
#pragma unroll
        for (int idx = 0; idx < 64; idx++) {
            float a = acc[idx];
            a += __shfl_xor_sync(0xffffffffu, a, 16);
            a += __shfl_xor_sync(0xffffffffu, a, 8);
            a += __shfl_xor_sync(0xffffffffu, a, 4);
            a += __shfl_xor_sync(0xffffffffu, a, 2);
            a += __shfl_xor_sync(0xffffffffu, a, 1);
            if (lane == 0) vred[wp*64 + idx] = a;
        }
        __syncthreads();

        if (t < 64) {
            float tot = 0.f;
#pragma unroll
            for (int w = 0; w < 8; w++) tot += vred[w*64 + t];
            int g = t >> 4, m = t & 15;
            d_outv[(((size_t)(b*G + g)*NPOS) + i*WDIM + j)*128 + m*HEADS + h] = tot / sum[g];
        }
        __syncthreads();
    }
}

// ---------------- final 1x1 conv: out[b][o][g][pos] ----------------
__global__ void out_kernel(const float* __restrict__ w_out,
                           const float* __restrict__ b_out,
                           float* __restrict__ out)
{
    __shared__ float wsh[64*129];
    int t = threadIdx.x;
    for (int idx = t; idx < 64*128; idx += 256) {
        int o = idx >> 7, c = idx & 127;
        wsh[o*129 + c] = w_out[idx];
    }
    __syncthreads();

    int bx = blockIdx.x;
    int chunk = bx % 14;
    int g = (bx / 14) % G;
    int b = bx / (14*G);

    int o  = t & 63;
    int pg = t >> 6;
    float bias = b_out[o];

    for (int pl = pg; pl < 56; pl += 4) {
        int pos = chunk*56 + pl;
        const float* xin = d_outv + ((size_t)(b*G + g)*NPOS + pos)*128;
        float acc = bias;
#pragma unroll 16
        for (int c = 0; c < 128; c++) acc += wsh[o*129 + c]*xin[c];
        out[(((size_t)(b*COUT + o))*G + g)*NPOS + pos] = acc;
    }
}

// ---------------- launch ----------------
extern "C" void kernel_launch(void* const* d_in, const int* in_sizes, int n_in,
                              void* d_out, int out_size)
{
    const float* x     = (const float*)d_in[0];
    const float* wq    = (const float*)d_in[1];
    const float* bq    = (const float*)d_in[2];
    const float* wk    = (const float*)d_in[3];
    const float* bk    = (const float*)d_in[4];
    const float* wv    = (const float*)d_in[5];
    const float* bv    = (const float*)d_in[6];
    const float* w_out = (const float*)d_in[7];
    const float* b_out = (const float*)d_in[8];
    const float* row_w1 = (const float*)d_in[9];
    const float* row_b1 = (const float*)d_in[10];
    const float* row_g  = (const float*)d_in[11];
    const float* row_be = (const float*)d_in[12];
    const float* row_w2 = (const float*)d_in[13];
    const float* row_b2 = (const float*)d_in[14];
    const float* col_w1 = (const float*)d_in[15];
    const float* col_b1 = (const float*)d_in[16];
    const float* col_g  = (const float*)d_in[17];
    const float* col_be = (const float*)d_in[18];
    const float* col_w2 = (const float*)d_in[19];
    const float* col_b2 = (const float*)d_in[20];
    // d_in[21], d_in[22] = ridx, cidx -- computed analytically in-kernel

    cudaFuncSetAttribute(attn_kernel,
                         cudaFuncAttributeMaxDynamicSharedMemorySize,
                         SMEM_FLOATS * sizeof(float));

    embed_kernel<<<1, 256>>>(row_w1, row_b1, row_g, row_be, row_w2, row_b2,
                             col_w1, col_b1, col_g, col_be, col_w2, col_b2);

    int qkv_threads = BATCH*128*NPOS;
    qkv_kernel<<<(qkv_threads + 255)/256, 256>>>(x, wq, bq, wk, bk, wv, bv);

    attn_kernel<<<BATCH*HEADS*WDIM, 256, SMEM_FLOATS*sizeof(float)>>>();

    out_kernel<<<BATCH*G*14, 256>>>(w_out, b_out, (float*)d_out);
}

// round 3
// speedup vs baseline: 3.0888x; 3.0888x over previous
#include <cuda_runtime.h>

#define BATCH 4
#define HEADS 8
#define MID 16
#define HALF 8
#define G 4
#define COUT 64
#define WDIM 28
#define NPOS 784
#define NREL 110
#define SCALE 0.5773502691896258f   // 1/sqrt(3)

// ---------------- device scratch ----------------
// q/k/v layout: [b][h][pos][16]  (m contiguous)
__device__ float d_q[BATCH*HEADS*NPOS*MID];
__device__ float d_k[BATCH*HEADS*NPOS*MID];
__device__ float d_v[BATCH*HEADS*NPOS*MID];
__device__ float d_Er[NREL*HALF];
__device__ float d_Ec[NREL*HALF];
__device__ float d_outv[BATCH*G*NPOS*(MID*HEADS)];   // [b][g][pos][m*8+h]

// ---------------- embedding MLP: 220 rows ----------------
__global__ void embed_kernel(
    const float* __restrict__ w1r, const float* __restrict__ b1r,
    const float* __restrict__ gr,  const float* __restrict__ ber,
    const float* __restrict__ w2r, const float* __restrict__ b2r,
    const float* __restrict__ w1c, const float* __restrict__ b1c,
    const float* __restrict__ gc,  const float* __restrict__ bec,
    const float* __restrict__ w2c, const float* __restrict__ b2c)
{
    int t = threadIdx.x;
    if (t >= 2*NREL) return;
    bool isRow = (t < NREL);
    int a = isRow ? t : t - NREL;
    const float* w1 = isRow ? w1r : w1c;
    const float* b1 = isRow ? b1r : b1c;
    const float* ga = isRow ? gr  : gc;
    const float* be = isRow ? ber : bec;
    const float* w2 = isRow ? w2r : w2c;
    const float* b2 = isRow ? b2r : b2c;

    float u;
    if (a < 55) u = a * (2.0f/54.0f) - 1.0f;
    else        u = -((a-55) * (2.0f/54.0f) - 1.0f);

    float h[16];
    float mu = 0.f;
#pragma unroll
    for (int c = 0; c < 16; c++) { h[c] = u*w1[c] + b1[c]; mu += h[c]; }
    mu *= (1.0f/16.0f);
    float var = 0.f;
#pragma unroll
    for (int c = 0; c < 16; c++) { float d = h[c]-mu; var += d*d; }
    var *= (1.0f/16.0f);
    float inv = rsqrtf(var + 1e-5f);
#pragma unroll
    for (int c = 0; c < 16; c++) {
        float hn = ga[c]*(h[c]-mu)*inv + be[c];
        h[c] = hn / (1.0f + expf(-hn));
    }
    float* out = isRow ? d_Er : d_Ec;
#pragma unroll
    for (int d = 0; d < HALF; d++) {
        float s = b2[d];
#pragma unroll
        for (int c = 0; c < 16; c++) s += h[c]*w2[d*16+c];
        out[a*HALF + d] = s;
    }
}

// ---------------- q/k/v 1x1 conv, output [b][h][pos][16] ----------------
__global__ void qkv_kernel(
    const float* __restrict__ x,
    const float* __restrict__ wq, const float* __restrict__ bq,
    const float* __restrict__ wk, const float* __restrict__ bk,
    const float* __restrict__ wv, const float* __restrict__ bv)
{
    int idx = blockIdx.x*blockDim.x + threadIdx.x;
    if (idx >= BATCH*HEADS*NPOS*4) return;
    int mg  = idx & 3;
    int r   = idx >> 2;
    int pos = r % NPOS;
    int r2  = r / NPOS;
    int h   = r2 & 7;
    int b   = r2 >> 3;

    float x0 = x[(b*3+0)*NPOS + pos];
    float x1 = x[(b*3+1)*NPOS + pos];
    float x2 = x[(b*3+2)*NPOS + pos];

    float4 qv, kv, vv;
    float* qp = (float*)&qv; float* kp = (float*)&kv; float* vp = (float*)&vv;
#pragma unroll
    for (int mi = 0; mi < 4; mi++) {
        int o = (mg*4 + mi)*8 + h;
        qp[mi] = bq[o] + wq[o*3+0]*x0 + wq[o*3+1]*x1 + wq[o*3+2]*x2;
        kp[mi] = bk[o] + wk[o*3+0]*x0 + wk[o*3+1]*x1 + wk[o*3+2]*x2;
        vp[mi] = bv[o] + wv[o*3+0]*x0 + wv[o*3+1]*x1 + wv[o*3+2]*x2;
    }
    size_t dst4 = ((size_t)(b*HEADS + h)*NPOS + pos)*4 + mg;
    ((float4*)d_q)[dst4] = qv;
    ((float4*)d_k)[dst4] = kv;
    ((float4*)d_v)[dst4] = vv;
}

// ---------------- fused attention: one CTA per (b,h,i), warp-per-j ----------------
// smem: ksh4[3136 float4] | vsh4[3136 float4] | ftab[7*220] | snorm
#define ATTN_SMEM_FLOATS (25088 + 7*220 + 4)
#define ATTN_SMEM_BYTES  (ATTN_SMEM_FLOATS*4)

#define RSTEP(B, NN) { unsigned up = lane & (B);                         \
    _Pragma("unroll") for (int v = 0; v < (NN); v++) {                   \
        float send = up ? acc[v] : acc[v+(NN)];                          \
        float recv = __shfl_xor_sync(0xffffffffu, send, (B));            \
        acc[v] = (up ? acc[v+(NN)] : acc[v]) + recv; } }

__global__ void __launch_bounds__(224, 2) attn_kernel()
{
    extern __shared__ float4 smem4[];
    float4* ksh4 = smem4;
    float4* vsh4 = smem4 + 3136;
    float*  smemf = (float*)smem4;
    float*  ftab  = smemf + 25088;
    int*    snorm = (int*)(smemf + 25088 + 7*220);

    int t    = threadIdx.x;
    int w    = t >> 5;
    int lane = t & 31;
    int bx = blockIdx.x;
    int i  = bx % WDIM;
    int h  = (bx / WDIM) % HEADS;
    int b  = bx / (WDIM*HEADS);

    const float4* gk4 = (const float4*)(d_k + (size_t)(b*HEADS + h)*NPOS*MID);
    const float4* gv4 = (const float4*)(d_v + (size_t)(b*HEADS + h)*NPOS*MID);
    const float*  gq  = d_q + (size_t)(b*HEADS + h)*NPOS*MID;

    if (t == 0) *snorm = 0;
    // load K,V: gmem idx = pos*4+mb -> smem [mb][pos]
    for (int idx = t; idx < 3136; idx += 224) {
        int mb = idx & 3, pos = idx >> 2;
        ksh4[mb*NPOS + pos] = gk4[idx];
        vsh4[mb*NPOS + pos] = gv4[idx];
    }
    __syncthreads();

    // max ||k||^2 over positions
    {
        float mx = 0.f;
        for (int pos = t; pos < NPOS; pos += 224) {
            float4 k0 = ksh4[pos], k1 = ksh4[NPOS+pos], k2 = ksh4[2*NPOS+pos], k3 = ksh4[3*NPOS+pos];
            float n2 = k0.x*k0.x + k0.y*k0.y + k0.z*k0.z + k0.w*k0.w
                     + k1.x*k1.x + k1.y*k1.y + k1.z*k1.z + k1.w*k1.w
                     + k2.x*k2.x + k2.y*k2.y + k2.z*k2.z + k2.w*k2.w
                     + k3.x*k3.x + k3.y*k3.y + k3.z*k3.z + k3.w*k3.w;
            mx = fmaxf(mx, n2);
        }
#pragma unroll
        for (int off = 16; off; off >>= 1) mx = fmaxf(mx, __shfl_xor_sync(0xffffffffu, mx, off));
        if (lane == 0) atomicMax(snorm, __float_as_int(mx));
    }
    __syncthreads();
    float maxknorm = sqrtf(__int_as_float(*snorm));

    float* fRw = ftab + w*220;
    float* fCw = fRw + NREL;

    for (int jj = 0; jj < 4; jj++) {
        int j = w + 7*jj;

        // q (scaled by 1/sqrt(3))
        float q[16];
        {
            const float4* gq4 = (const float4*)(gq + ((size_t)(i*WDIM + j))*16);
            float4 a0 = gq4[0], a1 = gq4[1], a2 = gq4[2], a3 = gq4[3];
            q[0]=a0.x*SCALE; q[1]=a0.y*SCALE; q[2]=a0.z*SCALE; q[3]=a0.w*SCALE;
            q[4]=a1.x*SCALE; q[5]=a1.y*SCALE; q[6]=a1.z*SCALE; q[7]=a1.w*SCALE;
            q[8]=a2.x*SCALE; q[9]=a2.y*SCALE; q[10]=a2.z*SCALE; q[11]=a2.w*SCALE;
            q[12]=a3.x*SCALE; q[13]=a3.y*SCALE; q[14]=a3.z*SCALE; q[15]=a3.w*SCALE;
        }
        float qn = 0.f;
#pragma unroll
        for (int m = 0; m < 16; m++) qn += q[m]*q[m];

        // per-warp lookup tables (scaled)
        __syncwarp();
        float tR = -1e30f, tC = -1e30f;
        for (int a = lane; a < NREL; a += 32) {
            const float4* er = (const float4*)(d_Er + a*8);
            float4 e0 = er[0], e1 = er[1];
            float s = q[0]*e0.x + q[1]*e0.y + q[2]*e0.z + q[3]*e0.w
                    + q[4]*e1.x + q[5]*e1.y + q[6]*e1.z + q[7]*e1.w;
            fRw[a] = s; tR = fmaxf(tR, s);
            const float4* ec = (const float4*)(d_Ec + a*8);
            float4 c0 = ec[0], c1 = ec[1];
            float sc = q[8]*c0.x + q[9]*c0.y + q[10]*c0.z + q[11]*c0.w
                     + q[12]*c1.x + q[13]*c1.y + q[14]*c1.z + q[15]*c1.w;
            fCw[a] = sc; tC = fmaxf(tC, sc);
        }
        __syncwarp();
#pragma unroll
        for (int off = 16; off; off >>= 1) {
            tR = fmaxf(tR, __shfl_xor_sync(0xffffffffu, tR, off));
            tC = fmaxf(tC, __shfl_xor_sync(0xffffffffu, tC, off));
        }
        // safe softmax shift (upper bound on any score)
        float M = sqrtf(qn)*maxknorm + tR + tC;

        float acc[64];
#pragma unroll
        for (int v = 0; v < 64; v++) acc[v] = 0.f;
        float sum0 = 0.f, sum1 = 0.f, sum2 = 0.f, sum3 = 0.f;

#pragma unroll 5
        for (int c = 0; c < 25; c++) {
            int pos = lane + 32*c;
            if (pos < NPOS) {
                float4 k0 = ksh4[pos], k1 = ksh4[NPOS+pos], k2 = ksh4[2*NPOS+pos], k3 = ksh4[3*NPOS+pos];
                float qk = q[0]*k0.x + q[1]*k0.y + q[2]*k0.z + q[3]*k0.w
                         + q[4]*k1.x + q[5]*k1.y + q[6]*k1.z + q[7]*k1.w
                         + q[8]*k2.x + q[9]*k2.y + q[10]*k2.z + q[11]*k2.w
                         + q[12]*k3.x + q[13]*k3.y + q[14]*k3.z + q[15]*k3.w - M;
                int kk = pos / WDIM;
                int ll = pos - kk*WDIM;
                int R = kk - i + 27;
                int C = ll - j + 27;
                float e0 = __expf(qk + fRw[R]    + fCw[C]);
                float e1 = __expf(qk + fRw[C+55] + fCw[R]);
                float e2 = __expf(qk + fRw[R+55] + fCw[C+55]);
                float e3 = __expf(qk + fRw[C]    + fCw[R+55]);
                sum0 += e0; sum1 += e1; sum2 += e2; sum3 += e3;
                float4 v0 = vsh4[pos], v1 = vsh4[NPOS+pos], v2 = vsh4[2*NPOS+pos], v3 = vsh4[3*NPOS+pos];
                float vv[16] = {v0.x,v0.y,v0.z,v0.w, v1.x,v1.y,v1.z,v1.w,
                                v2.x,v2.y,v2.z,v2.w, v3.x,v3.y,v3.z,v3.w};
#pragma unroll
                for (int m = 0; m < 16; m++) {
                    acc[ 0+m] += e0*vv[m];
                    acc[16+m] += e1*vv[m];
                    acc[32+m] += e2*vv[m];
                    acc[48+m] += e3*vv[m];
                }
            }
        }

        // warp-reduce sums
#pragma unroll
        for (int off = 16; off; off >>= 1) {
            sum0 += __shfl_xor_sync(0xffffffffu, sum0, off);
            sum1 += __shfl_xor_sync(0xffffffffu, sum1, off);
            sum2 += __shfl_xor_sync(0xffffffffu, sum2, off);
            sum3 += __shfl_xor_sync(0xffffffffu, sum3, off);
        }
        float sums[4] = {sum0, sum1, sum2, sum3};

        // value-halving warp reduce of 64 accumulators:
        // after 5 steps lane L holds values v=2L, 2L+1 fully reduced
        RSTEP(16, 32) RSTEP(8, 16) RSTEP(4, 8) RSTEP(2, 4) RSTEP(1, 2)

#pragma unroll
        for (int q2 = 0; q2 < 2; q2++) {
            int v = 2*lane + q2;
            int g = v >> 4, m = v & 15;
            d_outv[(((size_t)(b*G + g)*NPOS) + i*WDIM + j)*128 + m*8 + h] = acc[q2] / sums[g];
        }
    }
}

// ---------------- output 1x1 conv as tiled SGEMM ----------------
// C[12544 rows (b,g,pos), 64 cols o] = X[rows,128] * W^T ; block: 64 rows x 64 cols
#define OUT_SMEM_BYTES (2*128*65*4)
__global__ void __launch_bounds__(256) out_gemm(const float* __restrict__ wout,
                                                const float* __restrict__ bout,
                                                float* __restrict__ out)
{
    extern __shared__ float osh[];
    float* Xs = osh;            // [k][row] stride 65
    float* Ws = osh + 128*65;   // [k][col] stride 65

    int t  = threadIdx.x;
    int tx = t & 15;
    int ty = t >> 4;
    int Rbase = blockIdx.x * 64;

    // load X tile (64 rows x 128 ch), transpose into Xs[k][r]
    for (int it = t; it < 64*32; it += 256) {
        int r = it >> 5, c4 = it & 31;
        float4 val = ((const float4*)d_outv)[(size_t)(Rbase + r)*32 + c4];
        int c = c4*4;
        Xs[(c+0)*65 + r] = val.x;
        Xs[(c+1)*65 + r] = val.y;
        Xs[(c+2)*65 + r] = val.z;
        Xs[(c+3)*65 + r] = val.w;
    }
    // load W (64 o x 128 c), transpose into Ws[k][o]
    for (int it = t; it < 64*32; it += 256) {
        int o = it >> 5, c4 = it & 31;
        float4 val = ((const float4*)wout)[o*32 + c4];
        int c = c4*4;
        Ws[(c+0)*65 + o] = val.x;
        Ws[(c+1)*65 + o] = val.y;
        Ws[(c+2)*65 + o] = val.z;
        Ws[(c+3)*65 + o] = val.w;
    }
    __syncthreads();

    float accr[4][4];
#pragma unroll
    for (int a = 0; a < 4; a++)
#pragma unroll
        for (int c = 0; c < 4; c++) accr[a][c] = 0.f;

#pragma unroll 4
    for (int k = 0; k < 128; k++) {
        float av[4], bv[4];
#pragma unroll
        for (int ri = 0; ri < 4; ri++) av[ri] = Xs[k*65 + tx + 16*ri];
#pragma unroll
        for (int ci = 0; ci < 4; ci++) bv[ci] = Ws[k*65 + ty + 16*ci];
#pragma unroll
        for (int ri = 0; ri < 4; ri++)
#pragma unroll
            for (int ci = 0; ci < 4; ci++)
                accr[ri][ci] += av[ri]*bv[ci];
    }

#pragma unroll
    for (int ri = 0; ri < 4; ri++) {
        int R = Rbase + tx + 16*ri;
        int b = R / (G*NPOS);
        int rem = R - b*(G*NPOS);
        int g = rem / NPOS;
        int pos = rem - g*NPOS;
#pragma unroll
        for (int ci = 0; ci < 4; ci++) {
            int o = ty + 16*ci;
            out[(((size_t)(b*COUT + o))*G + g)*NPOS + pos] = accr[ri][ci] + bout[o];
        }
    }
}

// ---------------- launch ----------------
extern "C" void kernel_launch(void* const* d_in, const int* in_sizes, int n_in,
                              void* d_out, int out_size)
{
    const float* x     = (const float*)d_in[0];
    const float* wq    = (const float*)d_in[1];
    const float* bq    = (const float*)d_in[2];
    const float* wk    = (const float*)d_in[3];
    const float* bk    = (const float*)d_in[4];
    const float* wv    = (const float*)d_in[5];
    const float* bv    = (const float*)d_in[6];
    const float* w_out = (const float*)d_in[7];
    const float* b_out = (const float*)d_in[8];
    const float* row_w1 = (const float*)d_in[9];
    const float* row_b1 = (const float*)d_in[10];
    const float* row_g  = (const float*)d_in[11];
    const float* row_be = (const float*)d_in[12];
    const float* row_w2 = (const float*)d_in[13];
    const float* row_b2 = (const float*)d_in[14];
    const float* col_w1 = (const float*)d_in[15];
    const float* col_b1 = (const float*)d_in[16];
    const float* col_g  = (const float*)d_in[17];
    const float* col_be = (const float*)d_in[18];
    const float* col_w2 = (const float*)d_in[19];
    const float* col_b2 = (const float*)d_in[20];

    cudaFuncSetAttribute(attn_kernel, cudaFuncAttributeMaxDynamicSharedMemorySize, ATTN_SMEM_BYTES);
    cudaFuncSetAttribute(out_gemm,    cudaFuncAttributeMaxDynamicSharedMemorySize, OUT_SMEM_BYTES);

    embed_kernel<<<1, 256>>>(row_w1, row_b1, row_g, row_be, row_w2, row_b2,
                             col_w1, col_b1, col_g, col_be, col_w2, col_b2);

    int qkv_threads = BATCH*HEADS*NPOS*4;
    qkv_kernel<<<(qkv_threads + 255)/256, 256>>>(x, wq, bq, wk, bk, wv, bv);

    attn_kernel<<<BATCH*HEADS*WDIM, 224, ATTN_SMEM_BYTES>>>();

    out_gemm<<<196, 256, OUT_SMEM_BYTES>>>(w_out, b_out, (float*)d_out);
}